// round 5
// baseline (speedup 1.0000x reference)
#include <cuda_runtime.h>
#include <cuda_bf16.h>
#include <mma.h>

using namespace nvcuda;

// Problem constants (B=8, S=4096, D=1024, H=16 heads, head_dim=64)
#define NB 8
#define NS 4096
#define ND 1024
#define NH 16

// Scratch (static device arrays; no runtime allocation allowed)
__device__ float g_G[(size_t)NB * ND * ND];  // Gram matrices  X^T X
__device__ float g_U[(size_t)NB * ND * ND];  // U = G Wq^T
__device__ float g_P[(size_t)NB * ND * ND];  // P = blockdiag(Wv_h^T A_h)
__device__ float g_M[(size_t)NB * ND * ND];  // M = P Wo^T

// ---- fp32 -> bf16 hi/lo split, packed as 4 elements (uint2 = 4 bf16) ------
__device__ __forceinline__ void split4(float4 v, uint2& h, uint2& l) {
    __nv_bfloat162 h01 = __floats2bfloat162_rn(v.x, v.y);
    __nv_bfloat162 h23 = __floats2bfloat162_rn(v.z, v.w);
    float2 f01 = __bfloat1622float2(h01);
    float2 f23 = __bfloat1622float2(h23);
    __nv_bfloat162 l01 = __floats2bfloat162_rn(v.x - f01.x, v.y - f01.y);
    __nv_bfloat162 l23 = __floats2bfloat162_rn(v.z - f23.x, v.w - f23.y);
    h.x = *(unsigned*)&h01; h.y = *(unsigned*)&h23;
    l.x = *(unsigned*)&l01; l.y = *(unsigned*)&l23;
}

#define NLD 136   // ld for [16][128] n-wide bf16 tiles (pad 8)
#define KLD 16    // ld for [128][16] k-major bf16 tiles

typedef wmma::fragment<wmma::accumulator, 16, 16, 16, float> AccFrag;

// ---------------------------------------------------------------------------
// K1: G_b = X_b^T X_b  (symmetric: upper-tri 128x128 block pairs only)
// grid (36, 1, NB), block 256 (8 warps; warp tile 64x32), kTile=16,
// double-buffered, bf16-split wmma.
// C[i][j] = sum_y X[y][i] X[y][j] : A = col_major, B = row_major from the
// same [y][i]-layout tiles.
// ---------------------------------------------------------------------------
__global__ __launch_bounds__(256) void k_xtx(const float* __restrict__ X) {
    const int b = blockIdx.z;
    int p = blockIdx.x, pi = 0;
    while (p >= 8 - pi) { p -= 8 - pi; pi++; }
    const int bi = pi * 128, bj = (pi + p) * 128;
    const float* Xb = X + (size_t)b * NS * ND;

    __shared__ __nv_bfloat16 Ah[2][16][NLD], Al[2][16][NLD];
    __shared__ __nv_bfloat16 Bh[2][16][NLD], Bl[2][16][NLD];

    const int t = threadIdx.x;
    const int wid = t >> 5;
    const int m0 = (wid & 1) * 64, n0 = (wid >> 1) * 32;
    const int row0 = t >> 5;          // e>>5 for l=0 (rows 0..7), l=1 -> 8..15
    const int col4 = t & 31;          // float4 column index

    AccFrag acc[4][2];
#pragma unroll
    for (int i = 0; i < 4; i++)
#pragma unroll
        for (int j = 0; j < 2; j++) wmma::fill_fragment(acc[i][j], 0.0f);

    // preload tile 0
#pragma unroll
    for (int l = 0; l < 2; l++) {
        int row = row0 + l * 8;
        uint2 h, lo;
        split4(*(const float4*)&Xb[(size_t)row * ND + bi + col4 * 4], h, lo);
        *(uint2*)&Ah[0][row][col4 * 4] = h; *(uint2*)&Al[0][row][col4 * 4] = lo;
        split4(*(const float4*)&Xb[(size_t)row * ND + bj + col4 * 4], h, lo);
        *(uint2*)&Bh[0][row][col4 * 4] = h; *(uint2*)&Bl[0][row][col4 * 4] = lo;
    }
    __syncthreads();

    const int T = NS / 16;
    for (int ti = 0; ti < T; ti++) {
        const int cur = ti & 1;
        float4 ra[2], rb[2];
        const bool more = (ti + 1 < T);
        if (more) {
            int y0 = (ti + 1) * 16;
#pragma unroll
            for (int l = 0; l < 2; l++) {
                int row = row0 + l * 8;
                ra[l] = *(const float4*)&Xb[(size_t)(y0 + row) * ND + bi + col4 * 4];
                rb[l] = *(const float4*)&Xb[(size_t)(y0 + row) * ND + bj + col4 * 4];
            }
        }
        // --- MMA on current buffer ---
        {
            wmma::fragment<wmma::matrix_a, 16, 16, 16, __nv_bfloat16, wmma::col_major> ah[4], al[4];
            wmma::fragment<wmma::matrix_b, 16, 16, 16, __nv_bfloat16, wmma::row_major> bh[2], bl[2];
#pragma unroll
            for (int i = 0; i < 4; i++) {
                wmma::load_matrix_sync(ah[i], &Ah[cur][0][m0 + 16 * i], NLD);
                wmma::load_matrix_sync(al[i], &Al[cur][0][m0 + 16 * i], NLD);
            }
#pragma unroll
            for (int j = 0; j < 2; j++) {
                wmma::load_matrix_sync(bh[j], &Bh[cur][0][n0 + 16 * j], NLD);
                wmma::load_matrix_sync(bl[j], &Bl[cur][0][n0 + 16 * j], NLD);
            }
#pragma unroll
            for (int i = 0; i < 4; i++)
#pragma unroll
                for (int j = 0; j < 2; j++) {
                    wmma::mma_sync(acc[i][j], ah[i], bh[j], acc[i][j]);
                    wmma::mma_sync(acc[i][j], ah[i], bl[j], acc[i][j]);
                    wmma::mma_sync(acc[i][j], al[i], bh[j], acc[i][j]);
                }
        }
        if (more) {
            int nxt = cur ^ 1;
#pragma unroll
            for (int l = 0; l < 2; l++) {
                int row = row0 + l * 8;
                uint2 h, lo;
                split4(ra[l], h, lo);
                *(uint2*)&Ah[nxt][row][col4 * 4] = h; *(uint2*)&Al[nxt][row][col4 * 4] = lo;
                split4(rb[l], h, lo);
                *(uint2*)&Bh[nxt][row][col4 * 4] = h; *(uint2*)&Bl[nxt][row][col4 * 4] = lo;
            }
        }
        __syncthreads();
    }

    float* Gb = g_G + (size_t)b * ND * ND;
#pragma unroll
    for (int i = 0; i < 4; i++)
#pragma unroll
        for (int j = 0; j < 2; j++) {
            int mg = bi + m0 + 16 * i, ng = bj + n0 + 16 * j;
            wmma::store_matrix_sync(&Gb[(size_t)mg * ND + ng], acc[i][j], ND, wmma::mem_row_major);
            if (bi != bj)  // mirror: G[ng..][mg..] = block^T
                wmma::store_matrix_sync(&Gb[(size_t)ng * ND + mg], acc[i][j], ND, wmma::mem_col_major);
        }
}

// ---------------------------------------------------------------------------
// K2/K4: C_b = A_b * Bw^T  (1024^3 per batch)
// mode 0: A=g_G, C=g_U, Bw=Wq     mode 1: A=g_P, C=g_M, Bw=Wo
// grid (8, 8, NB), block 256, kTile=16, double-buffered, bf16-split wmma.
// A tile [128][16] row-major (matrix_a row_major), B tile [128][16]
// (matrix_b col_major: column j of logical k x n = Bw row j, contiguous).
// ---------------------------------------------------------------------------
__global__ __launch_bounds__(256) void k_abt(const float* __restrict__ Bw, int mode) {
    const int b = blockIdx.z;
    const int bi = blockIdx.x * 128, bj = blockIdx.y * 128;
    const float* Ab = (mode == 0 ? g_G : g_P) + (size_t)b * ND * ND;
    float* Cb       = (mode == 0 ? g_U : g_M) + (size_t)b * ND * ND;

    __shared__ __nv_bfloat16 Ah[2][128][KLD], Al[2][128][KLD];
    __shared__ __nv_bfloat16 Bh[2][128][KLD], Bl[2][128][KLD];

    const int t = threadIdx.x;
    const int wid = t >> 5;
    const int m0 = (wid & 1) * 64, n0 = (wid >> 1) * 32;

    AccFrag acc[4][2];
#pragma unroll
    for (int i = 0; i < 4; i++)
#pragma unroll
        for (int j = 0; j < 2; j++) wmma::fill_fragment(acc[i][j], 0.0f);

#pragma unroll
    for (int l = 0; l < 2; l++) {
        int e = t + l * 256;
        int r = e >> 2, kg = (e & 3) << 2;
        uint2 h, lo;
        split4(*(const float4*)&Ab[(size_t)(bi + r) * ND + kg], h, lo);
        *(uint2*)&Ah[0][r][kg] = h; *(uint2*)&Al[0][r][kg] = lo;
        split4(*(const float4*)&Bw[(size_t)(bj + r) * ND + kg], h, lo);
        *(uint2*)&Bh[0][r][kg] = h; *(uint2*)&Bl[0][r][kg] = lo;
    }
    __syncthreads();

    const int T = ND / 16;
    for (int ti = 0; ti < T; ti++) {
        const int cur = ti & 1;
        float4 ra[2], rb[2];
        const bool more = (ti + 1 < T);
        if (more) {
            int k0 = (ti + 1) * 16;
#pragma unroll
            for (int l = 0; l < 2; l++) {
                int e = t + l * 256;
                int r = e >> 2, kg = (e & 3) << 2;
                ra[l] = *(const float4*)&Ab[(size_t)(bi + r) * ND + k0 + kg];
                rb[l] = *(const float4*)&Bw[(size_t)(bj + r) * ND + k0 + kg];
            }
        }
        {
            wmma::fragment<wmma::matrix_a, 16, 16, 16, __nv_bfloat16, wmma::row_major> ah[4], al[4];
            wmma::fragment<wmma::matrix_b, 16, 16, 16, __nv_bfloat16, wmma::col_major> bh[2], bl[2];
#pragma unroll
            for (int i = 0; i < 4; i++) {
                wmma::load_matrix_sync(ah[i], &Ah[cur][m0 + 16 * i][0], KLD);
                wmma::load_matrix_sync(al[i], &Al[cur][m0 + 16 * i][0], KLD);
            }
#pragma unroll
            for (int j = 0; j < 2; j++) {
                wmma::load_matrix_sync(bh[j], &Bh[cur][n0 + 16 * j][0], KLD);
                wmma::load_matrix_sync(bl[j], &Bl[cur][n0 + 16 * j][0], KLD);
            }
#pragma unroll
            for (int i = 0; i < 4; i++)
#pragma unroll
                for (int j = 0; j < 2; j++) {
                    wmma::mma_sync(acc[i][j], ah[i], bh[j], acc[i][j]);
                    wmma::mma_sync(acc[i][j], ah[i], bl[j], acc[i][j]);
                    wmma::mma_sync(acc[i][j], al[i], bh[j], acc[i][j]);
                }
        }
        if (more) {
            int nxt = cur ^ 1;
#pragma unroll
            for (int l = 0; l < 2; l++) {
                int e = t + l * 256;
                int r = e >> 2, kg = (e & 3) << 2;
                uint2 h, lo;
                split4(ra[l], h, lo);
                *(uint2*)&Ah[nxt][r][kg] = h; *(uint2*)&Al[nxt][r][kg] = lo;
                split4(rb[l], h, lo);
                *(uint2*)&Bh[nxt][r][kg] = h; *(uint2*)&Bl[nxt][r][kg] = lo;
            }
        }
        __syncthreads();
    }

#pragma unroll
    for (int i = 0; i < 4; i++)
#pragma unroll
        for (int j = 0; j < 2; j++)
            wmma::store_matrix_sync(&Cb[(size_t)(bi + m0 + 16 * i) * ND + bj + n0 + 16 * j],
                                    acc[i][j], ND, wmma::mem_row_major);
}

// ---------------------------------------------------------------------------
// K3: per (head, batch): S = Wk_h U_h / 8 ; A = softmax_rows(S) ;
//     P_h = Wv_h^T A   (tiny: ~1% of FLOPs, stays fp32 SIMT)
// grid (NH, NB), block 256
// ---------------------------------------------------------------------------
__global__ __launch_bounds__(256, 2) void k_head(const float* __restrict__ Wk,
                                                 const float* __restrict__ Wv) {
    const int h = blockIdx.x, b = blockIdx.y;
    const float* Ub = g_U + (size_t)b * ND * ND;
    float* Pb       = g_P + (size_t)b * ND * ND;

    __shared__ float Ks[64][64];
    __shared__ float Us[64][64];
    __shared__ float Ss[64][64];

    const int t = threadIdx.x;
    const int tk = t >> 4, tq = t & 15;

    float acc[4][4];
#pragma unroll
    for (int u = 0; u < 4; u++)
#pragma unroll
        for (int v = 0; v < 4; v++) acc[u][v] = 0.f;

    for (int i0 = 0; i0 < ND; i0 += 64) {
#pragma unroll
        for (int l = 0; l < 4; l++) {
            int e = t + l * 256;
            int k = e >> 4, ig = (e & 15) << 2;
            float4 v = *(const float4*)&Wk[(size_t)(h * 64 + k) * ND + i0 + ig];
            Ks[ig + 0][k] = v.x; Ks[ig + 1][k] = v.y;
            Ks[ig + 2][k] = v.z; Ks[ig + 3][k] = v.w;
            *(float4*)&Us[k][ig] =
                *(const float4*)&Ub[(size_t)(i0 + k) * ND + h * 64 + ig];
        }
        __syncthreads();
#pragma unroll
        for (int ii = 0; ii < 64; ii++) {
            float a[4], bb[4];
            *(float4*)a  = *(float4*)&Ks[ii][tk * 4];
            *(float4*)bb = *(float4*)&Us[ii][tq * 4];
#pragma unroll
            for (int u = 0; u < 4; u++)
#pragma unroll
                for (int v = 0; v < 4; v++) acc[u][v] += a[u] * bb[v];
        }
        __syncthreads();
    }
#pragma unroll
    for (int u = 0; u < 4; u++)
#pragma unroll
        for (int v = 0; v < 4; v++)
            Ss[tk * 4 + u][tq * 4 + v] = acc[u][v] * 0.125f;  // 1/sqrt(64)
    __syncthreads();

    if (t < 64) {
        float m = -1e30f;
#pragma unroll 4
        for (int q = 0; q < 64; q++) m = fmaxf(m, Ss[t][q]);
        float s = 0.f;
#pragma unroll 4
        for (int q = 0; q < 64; q++) { float e = __expf(Ss[t][q] - m); Ss[t][q] = e; s += e; }
        float inv = 1.0f / s;
#pragma unroll 4
        for (int q = 0; q < 64; q++) Ss[t][q] *= inv;
    }
    __syncthreads();

    for (int i0 = 0; i0 < ND; i0 += 64) {
#pragma unroll
        for (int l = 0; l < 4; l++) {
            int e = t + l * 256;
            int k = e >> 4, ig = (e & 15) << 2;
            *(float4*)&Ks[k][ig] =
                *(const float4*)&Wv[(size_t)(h * 64 + k) * ND + i0 + ig];
        }
        __syncthreads();
        float acc2[4][4];
#pragma unroll
        for (int u = 0; u < 4; u++)
#pragma unroll
            for (int v = 0; v < 4; v++) acc2[u][v] = 0.f;
#pragma unroll
        for (int k = 0; k < 64; k++) {
            float a[4], bb[4];
            *(float4*)a  = *(float4*)&Ks[k][tk * 4];
            *(float4*)bb = *(float4*)&Ss[k][tq * 4];
#pragma unroll
            for (int u = 0; u < 4; u++)
#pragma unroll
                for (int v = 0; v < 4; v++) acc2[u][v] += a[u] * bb[v];
        }
        __syncthreads();
#pragma unroll
        for (int u = 0; u < 4; u++)
#pragma unroll
            for (int v = 0; v < 4; v++)
                Pb[(size_t)(i0 + tk * 4 + u) * ND + h * 64 + tq * 4 + v] = acc2[u][v];
    }
}

// ---------------------------------------------------------------------------
// K5: Y_b = X_b * M_b  (4096x1024x1024 per batch)
// grid (32, 8, NB), block 256, kTile=16, double-buffered, bf16-split wmma.
// A tile [128][16] (matrix_a row_major), B tile [16][128] (matrix_b row_major).
// ---------------------------------------------------------------------------
__global__ __launch_bounds__(256) void k_xm(const float* __restrict__ X,
                                            float* __restrict__ Y) {
    const int b = blockIdx.z;
    const int bs = blockIdx.x * 128, bo = blockIdx.y * 128;
    const float* Xb = X + (size_t)b * NS * ND;
    const float* Mb = g_M + (size_t)b * ND * ND;
    float* Yb = Y + (size_t)b * NS * ND;

    __shared__ __nv_bfloat16 Ah[2][128][KLD], Al[2][128][KLD];
    __shared__ __nv_bfloat16 Bh[2][16][NLD], Bl[2][16][NLD];

    const int t = threadIdx.x;
    const int wid = t >> 5;
    const int m0 = (wid & 1) * 64, n0 = (wid >> 1) * 32;

    AccFrag acc[4][2];
#pragma unroll
    for (int i = 0; i < 4; i++)
#pragma unroll
        for (int j = 0; j < 2; j++) wmma::fill_fragment(acc[i][j], 0.0f);

#pragma unroll
    for (int l = 0; l < 2; l++) {
        int e = t + l * 256;
        int r = e >> 2, kg = (e & 3) << 2;
        uint2 h, lo;
        split4(*(const float4*)&Xb[(size_t)(bs + r) * ND + kg], h, lo);
        *(uint2*)&Ah[0][r][kg] = h; *(uint2*)&Al[0][r][kg] = lo;
        int row = e >> 5, col4 = e & 31;
        split4(*(const float4*)&Mb[(size_t)row * ND + bo + col4 * 4], h, lo);
        *(uint2*)&Bh[0][row][col4 * 4] = h; *(uint2*)&Bl[0][row][col4 * 4] = lo;
    }
    __syncthreads();

    const int T = ND / 16;
    for (int ti = 0; ti < T; ti++) {
        const int cur = ti & 1;
        float4 ra[2], rb[2];
        const bool more = (ti + 1 < T);
        if (more) {
            int d0 = (ti + 1) * 16;
#pragma unroll
            for (int l = 0; l < 2; l++) {
                int e = t + l * 256;
                int r = e >> 2, kg = (e & 3) << 2;
                ra[l] = *(const float4*)&Xb[(size_t)(bs + r) * ND + d0 + kg];
                int row = e >> 5, col4 = e & 31;
                rb[l] = *(const float4*)&Mb[(size_t)(d0 + row) * ND + bo + col4 * 4];
            }
        }
        {
            wmma::fragment<wmma::matrix_a, 16, 16, 16, __nv_bfloat16, wmma::row_major> ah[4], al[4];
            wmma::fragment<wmma::matrix_b, 16, 16, 16, __nv_bfloat16, wmma::row_major> bh[2], bl[2];
#pragma unroll
            for (int i = 0; i < 4; i++) {
                wmma::load_matrix_sync(ah[i], &Ah[cur][m0 + 16 * i][0], KLD);
                wmma::load_matrix_sync(al[i], &Al[cur][m0 + 16 * i][0], KLD);
            }
#pragma unroll
            for (int j = 0; j < 2; j++) {
                wmma::load_matrix_sync(bh[j], &Bh[cur][0][n0 + 16 * j], NLD);
                wmma::load_matrix_sync(bl[j], &Bl[cur][0][n0 + 16 * j], NLD);
            }
#pragma unroll
            for (int i = 0; i < 4; i++)
#pragma unroll
                for (int j = 0; j < 2; j++) {
                    wmma::mma_sync(acc[i][j], ah[i], bh[j], acc[i][j]);
                    wmma::mma_sync(acc[i][j], ah[i], bl[j], acc[i][j]);
                    wmma::mma_sync(acc[i][j], al[i], bh[j], acc[i][j]);
                }
        }
        if (more) {
            int nxt = cur ^ 1;
#pragma unroll
            for (int l = 0; l < 2; l++) {
                int e = t + l * 256;
                int r = e >> 2, kg = (e & 3) << 2;
                uint2 h, lo;
                split4(ra[l], h, lo);
                *(uint2*)&Ah[nxt][r][kg] = h; *(uint2*)&Al[nxt][r][kg] = lo;
                int row = e >> 5, col4 = e & 31;
                split4(rb[l], h, lo);
                *(uint2*)&Bh[nxt][row][col4 * 4] = h; *(uint2*)&Bl[nxt][row][col4 * 4] = lo;
            }
        }
        __syncthreads();
    }

#pragma unroll
    for (int i = 0; i < 4; i++)
#pragma unroll
        for (int j = 0; j < 2; j++)
            wmma::store_matrix_sync(&Yb[(size_t)(bs + m0 + 16 * i) * ND + bo + n0 + 16 * j],
                                    acc[i][j], ND, wmma::mem_row_major);
}

// ---------------------------------------------------------------------------
extern "C" void kernel_launch(void* const* d_in, const int* in_sizes, int n_in,
                              void* d_out, int out_size) {
    const float* x  = (const float*)d_in[0];
    const float* Wq = (const float*)d_in[1];
    const float* Wk = (const float*)d_in[2];
    const float* Wv = (const float*)d_in[3];
    const float* Wo = (const float*)d_in[4];
    float* y = (float*)d_out;

    // 1) Gram matrices: G_b = X_b^T X_b (symmetric, 36 block pairs)
    k_xtx<<<dim3(36, 1, NB), 256>>>(x);
    // 2) U_b = G_b Wq^T
    k_abt<<<dim3(8, 8, NB), 256>>>(Wq, 0);
    // 3) per-head scores + softmax + P_h = Wv_h^T A_h
    k_head<<<dim3(NH, NB), 256>>>(Wk, Wv);
    // 4) M_b = P_b Wo^T
    k_abt<<<dim3(8, 8, NB), 256>>>(Wo, 1);
    // 5) Y_b = X_b M_b
    k_xm<<<dim3(32, 8, NB), 256>>>(x, y);
}

// round 6
// speedup vs baseline: 1.3641x; 1.3641x over previous
#include <cuda_runtime.h>
#include <cuda_bf16.h>
#include <mma.h>

using namespace nvcuda;

// Problem constants (B=8, S=4096, D=1024, H=16 heads, head_dim=64)
#define NB 8
#define NS 4096
#define ND 1024
#define NH 16

// Scratch (static device arrays; no runtime allocation allowed)
__device__ float g_G[(size_t)NB * ND * ND];  // Gram matrices  X^T X
__device__ float g_U[(size_t)NB * ND * ND];  // U = G Wq^T
__device__ float g_P[(size_t)NB * ND * ND];  // P = blockdiag(Wv_h^T A_h)
__device__ float g_M[(size_t)NB * ND * ND];  // M = P Wo^T

// ---- fp32 -> bf16 hi/lo split, packed as 4 elements (uint2 = 4 bf16) ------
__device__ __forceinline__ void split4(float4 v, uint2& h, uint2& l) {
    __nv_bfloat162 h01 = __floats2bfloat162_rn(v.x, v.y);
    __nv_bfloat162 h23 = __floats2bfloat162_rn(v.z, v.w);
    float2 f01 = __bfloat1622float2(h01);
    float2 f23 = __bfloat1622float2(h23);
    __nv_bfloat162 l01 = __floats2bfloat162_rn(v.x - f01.x, v.y - f01.y);
    __nv_bfloat162 l23 = __floats2bfloat162_rn(v.z - f23.x, v.w - f23.y);
    h.x = *(unsigned*)&h01; h.y = *(unsigned*)&h23;
    l.x = *(unsigned*)&l01; l.y = *(unsigned*)&l23;
}

#define NLD 136   // ld for [16][128] n-wide bf16 tiles (272B rows: conflict-free)
#define KLD 24    // ld for [128][16] k-major bf16 tiles (48B rows: degree-2 vs 4)

typedef wmma::fragment<wmma::accumulator, 16, 16, 16, float> AccFrag;

// ---------------------------------------------------------------------------
// K1: G_b = X_b^T X_b  (symmetric: upper-tri 128x128 block pairs only)
// grid (36, 1, NB), block 256 (8 warps; warp tile 64x32), kTile=16,
// double-buffered, bf16-split wmma.
// ---------------------------------------------------------------------------
__global__ __launch_bounds__(256) void k_xtx(const float* __restrict__ X) {
    const int b = blockIdx.z;
    int p = blockIdx.x, pi = 0;
    while (p >= 8 - pi) { p -= 8 - pi; pi++; }
    const int bi = pi * 128, bj = (pi + p) * 128;
    const float* Xb = X + (size_t)b * NS * ND;

    __shared__ __nv_bfloat16 Ah[2][16][NLD], Al[2][16][NLD];
    __shared__ __nv_bfloat16 Bh[2][16][NLD], Bl[2][16][NLD];

    const int t = threadIdx.x;
    const int wid = t >> 5;
    const int m0 = (wid & 1) * 64, n0 = (wid >> 1) * 32;
    const int row0 = t >> 5;
    const int col4 = t & 31;

    AccFrag acc[4][2];
#pragma unroll
    for (int i = 0; i < 4; i++)
#pragma unroll
        for (int j = 0; j < 2; j++) wmma::fill_fragment(acc[i][j], 0.0f);

#pragma unroll
    for (int l = 0; l < 2; l++) {
        int row = row0 + l * 8;
        uint2 h, lo;
        split4(*(const float4*)&Xb[(size_t)row * ND + bi + col4 * 4], h, lo);
        *(uint2*)&Ah[0][row][col4 * 4] = h; *(uint2*)&Al[0][row][col4 * 4] = lo;
        split4(*(const float4*)&Xb[(size_t)row * ND + bj + col4 * 4], h, lo);
        *(uint2*)&Bh[0][row][col4 * 4] = h; *(uint2*)&Bl[0][row][col4 * 4] = lo;
    }
    __syncthreads();

    const int T = NS / 16;
    for (int ti = 0; ti < T; ti++) {
        const int cur = ti & 1;
        float4 ra[2], rb[2];
        const bool more = (ti + 1 < T);
        if (more) {
            int y0 = (ti + 1) * 16;
#pragma unroll
            for (int l = 0; l < 2; l++) {
                int row = row0 + l * 8;
                ra[l] = *(const float4*)&Xb[(size_t)(y0 + row) * ND + bi + col4 * 4];
                rb[l] = *(const float4*)&Xb[(size_t)(y0 + row) * ND + bj + col4 * 4];
            }
        }
        {
            wmma::fragment<wmma::matrix_a, 16, 16, 16, __nv_bfloat16, wmma::col_major> ah[4], al[4];
            wmma::fragment<wmma::matrix_b, 16, 16, 16, __nv_bfloat16, wmma::row_major> bh[2], bl[2];
#pragma unroll
            for (int i = 0; i < 4; i++) {
                wmma::load_matrix_sync(ah[i], &Ah[cur][0][m0 + 16 * i], NLD);
                wmma::load_matrix_sync(al[i], &Al[cur][0][m0 + 16 * i], NLD);
            }
#pragma unroll
            for (int j = 0; j < 2; j++) {
                wmma::load_matrix_sync(bh[j], &Bh[cur][0][n0 + 16 * j], NLD);
                wmma::load_matrix_sync(bl[j], &Bl[cur][0][n0 + 16 * j], NLD);
            }
#pragma unroll
            for (int i = 0; i < 4; i++)
#pragma unroll
                for (int j = 0; j < 2; j++) {
                    wmma::mma_sync(acc[i][j], ah[i], bh[j], acc[i][j]);
                    wmma::mma_sync(acc[i][j], ah[i], bl[j], acc[i][j]);
                    wmma::mma_sync(acc[i][j], al[i], bh[j], acc[i][j]);
                }
        }
        if (more) {
            int nxt = cur ^ 1;
#pragma unroll
            for (int l = 0; l < 2; l++) {
                int row = row0 + l * 8;
                uint2 h, lo;
                split4(ra[l], h, lo);
                *(uint2*)&Ah[nxt][row][col4 * 4] = h; *(uint2*)&Al[nxt][row][col4 * 4] = lo;
                split4(rb[l], h, lo);
                *(uint2*)&Bh[nxt][row][col4 * 4] = h; *(uint2*)&Bl[nxt][row][col4 * 4] = lo;
            }
        }
        __syncthreads();
    }

    float* Gb = g_G + (size_t)b * ND * ND;
#pragma unroll
    for (int i = 0; i < 4; i++)
#pragma unroll
        for (int j = 0; j < 2; j++) {
            int mg = bi + m0 + 16 * i, ng = bj + n0 + 16 * j;
            wmma::store_matrix_sync(&Gb[(size_t)mg * ND + ng], acc[i][j], ND, wmma::mem_row_major);
            if (bi != bj)
                wmma::store_matrix_sync(&Gb[(size_t)ng * ND + mg], acc[i][j], ND, wmma::mem_col_major);
        }
}

// ---------------------------------------------------------------------------
// K2/K4: C_b = A_b * Bw^T  (1024^3 per batch)
// mode 0: A=g_G, C=g_U, Bw=Wq     mode 1: A=g_P, C=g_M, Bw=Wo
// grid (8, 8, NB), block 256, kTile=16, double-buffered, bf16-split wmma.
// ---------------------------------------------------------------------------
__global__ __launch_bounds__(256) void k_abt(const float* __restrict__ Bw, int mode) {
    const int b = blockIdx.z;
    const int bi = blockIdx.x * 128, bj = blockIdx.y * 128;
    const float* Ab = (mode == 0 ? g_G : g_P) + (size_t)b * ND * ND;
    float* Cb       = (mode == 0 ? g_U : g_M) + (size_t)b * ND * ND;

    __shared__ __nv_bfloat16 Ah[2][128][KLD], Al[2][128][KLD];
    __shared__ __nv_bfloat16 Bh[2][128][KLD], Bl[2][128][KLD];

    const int t = threadIdx.x;
    const int wid = t >> 5;
    const int m0 = (wid & 1) * 64, n0 = (wid >> 1) * 32;

    AccFrag acc[4][2];
#pragma unroll
    for (int i = 0; i < 4; i++)
#pragma unroll
        for (int j = 0; j < 2; j++) wmma::fill_fragment(acc[i][j], 0.0f);

#pragma unroll
    for (int l = 0; l < 2; l++) {
        int e = t + l * 256;
        int r = e >> 2, kg = (e & 3) << 2;
        uint2 h, lo;
        split4(*(const float4*)&Ab[(size_t)(bi + r) * ND + kg], h, lo);
        *(uint2*)&Ah[0][r][kg] = h; *(uint2*)&Al[0][r][kg] = lo;
        split4(*(const float4*)&Bw[(size_t)(bj + r) * ND + kg], h, lo);
        *(uint2*)&Bh[0][r][kg] = h; *(uint2*)&Bl[0][r][kg] = lo;
    }
    __syncthreads();

    const int T = ND / 16;
    for (int ti = 0; ti < T; ti++) {
        const int cur = ti & 1;
        float4 ra[2], rb[2];
        const bool more = (ti + 1 < T);
        if (more) {
            int k0 = (ti + 1) * 16;
#pragma unroll
            for (int l = 0; l < 2; l++) {
                int e = t + l * 256;
                int r = e >> 2, kg = (e & 3) << 2;
                ra[l] = *(const float4*)&Ab[(size_t)(bi + r) * ND + k0 + kg];
                rb[l] = *(const float4*)&Bw[(size_t)(bj + r) * ND + k0 + kg];
            }
        }
        {
            wmma::fragment<wmma::matrix_a, 16, 16, 16, __nv_bfloat16, wmma::row_major> ah[4], al[4];
            wmma::fragment<wmma::matrix_b, 16, 16, 16, __nv_bfloat16, wmma::col_major> bh[2], bl[2];
#pragma unroll
            for (int i = 0; i < 4; i++) {
                wmma::load_matrix_sync(ah[i], &Ah[cur][m0 + 16 * i][0], KLD);
                wmma::load_matrix_sync(al[i], &Al[cur][m0 + 16 * i][0], KLD);
            }
#pragma unroll
            for (int j = 0; j < 2; j++) {
                wmma::load_matrix_sync(bh[j], &Bh[cur][n0 + 16 * j][0], KLD);
                wmma::load_matrix_sync(bl[j], &Bl[cur][n0 + 16 * j][0], KLD);
            }
#pragma unroll
            for (int i = 0; i < 4; i++)
#pragma unroll
                for (int j = 0; j < 2; j++) {
                    wmma::mma_sync(acc[i][j], ah[i], bh[j], acc[i][j]);
                    wmma::mma_sync(acc[i][j], ah[i], bl[j], acc[i][j]);
                    wmma::mma_sync(acc[i][j], al[i], bh[j], acc[i][j]);
                }
        }
        if (more) {
            int nxt = cur ^ 1;
#pragma unroll
            for (int l = 0; l < 2; l++) {
                int e = t + l * 256;
                int r = e >> 2, kg = (e & 3) << 2;
                uint2 h, lo;
                split4(ra[l], h, lo);
                *(uint2*)&Ah[nxt][r][kg] = h; *(uint2*)&Al[nxt][r][kg] = lo;
                split4(rb[l], h, lo);
                *(uint2*)&Bh[nxt][r][kg] = h; *(uint2*)&Bl[nxt][r][kg] = lo;
            }
        }
        __syncthreads();
    }

#pragma unroll
    for (int i = 0; i < 4; i++)
#pragma unroll
        for (int j = 0; j < 2; j++)
            wmma::store_matrix_sync(&Cb[(size_t)(bi + m0 + 16 * i) * ND + bj + n0 + 16 * j],
                                    acc[i][j], ND, wmma::mem_row_major);
}

// ---------------------------------------------------------------------------
// K3: per (head, batch): S = Wk_h U_h / 8 ; A = softmax_rows(S) ;
//     P_h = Wv_h^T A   (tiny: ~1% of FLOPs, stays fp32 SIMT)
// grid (NH, NB), block 256
// ---------------------------------------------------------------------------
__global__ __launch_bounds__(256, 2) void k_head(const float* __restrict__ Wk,
                                                 const float* __restrict__ Wv) {
    const int h = blockIdx.x, b = blockIdx.y;
    const float* Ub = g_U + (size_t)b * ND * ND;
    float* Pb       = g_P + (size_t)b * ND * ND;

    __shared__ float Ks[64][64];
    __shared__ float Us[64][64];
    __shared__ float Ss[64][64];

    const int t = threadIdx.x;
    const int tk = t >> 4, tq = t & 15;

    float acc[4][4];
#pragma unroll
    for (int u = 0; u < 4; u++)
#pragma unroll
        for (int v = 0; v < 4; v++) acc[u][v] = 0.f;

    for (int i0 = 0; i0 < ND; i0 += 64) {
#pragma unroll
        for (int l = 0; l < 4; l++) {
            int e = t + l * 256;
            int k = e >> 4, ig = (e & 15) << 2;
            float4 v = *(const float4*)&Wk[(size_t)(h * 64 + k) * ND + i0 + ig];
            Ks[ig + 0][k] = v.x; Ks[ig + 1][k] = v.y;
            Ks[ig + 2][k] = v.z; Ks[ig + 3][k] = v.w;
            *(float4*)&Us[k][ig] =
                *(const float4*)&Ub[(size_t)(i0 + k) * ND + h * 64 + ig];
        }
        __syncthreads();
#pragma unroll
        for (int ii = 0; ii < 64; ii++) {
            float a[4], bb[4];
            *(float4*)a  = *(float4*)&Ks[ii][tk * 4];
            *(float4*)bb = *(float4*)&Us[ii][tq * 4];
#pragma unroll
            for (int u = 0; u < 4; u++)
#pragma unroll
                for (int v = 0; v < 4; v++) acc[u][v] += a[u] * bb[v];
        }
        __syncthreads();
    }
#pragma unroll
    for (int u = 0; u < 4; u++)
#pragma unroll
        for (int v = 0; v < 4; v++)
            Ss[tk * 4 + u][tq * 4 + v] = acc[u][v] * 0.125f;  // 1/sqrt(64)
    __syncthreads();

    if (t < 64) {
        float m = -1e30f;
#pragma unroll 4
        for (int q = 0; q < 64; q++) m = fmaxf(m, Ss[t][q]);
        float s = 0.f;
#pragma unroll 4
        for (int q = 0; q < 64; q++) { float e = __expf(Ss[t][q] - m); Ss[t][q] = e; s += e; }
        float inv = 1.0f / s;
#pragma unroll 4
        for (int q = 0; q < 64; q++) Ss[t][q] *= inv;
    }
    __syncthreads();

    for (int i0 = 0; i0 < ND; i0 += 64) {
#pragma unroll
        for (int l = 0; l < 4; l++) {
            int e = t + l * 256;
            int k = e >> 4, ig = (e & 15) << 2;
            *(float4*)&Ks[k][ig] =
                *(const float4*)&Wv[(size_t)(h * 64 + k) * ND + i0 + ig];
        }
        __syncthreads();
        float acc2[4][4];
#pragma unroll
        for (int u = 0; u < 4; u++)
#pragma unroll
            for (int v = 0; v < 4; v++) acc2[u][v] = 0.f;
#pragma unroll
        for (int k = 0; k < 64; k++) {
            float a[4], bb[4];
            *(float4*)a  = *(float4*)&Ks[k][tk * 4];
            *(float4*)bb = *(float4*)&Ss[k][tq * 4];
#pragma unroll
            for (int u = 0; u < 4; u++)
#pragma unroll
                for (int v = 0; v < 4; v++) acc2[u][v] += a[u] * bb[v];
        }
        __syncthreads();
#pragma unroll
        for (int u = 0; u < 4; u++)
#pragma unroll
            for (int v = 0; v < 4; v++)
                Pb[(size_t)(i0 + tk * 4 + u) * ND + h * 64 + tq * 4 + v] = acc2[u][v];
    }
}

// ---------------------------------------------------------------------------
// K5: Y_b = X_b * M_b  (4096x1024x1024 per batch)
// grid (32, 8, NB), block 256, kTile=16, double-buffered, bf16-split wmma.
// ---------------------------------------------------------------------------
__global__ __launch_bounds__(256) void k_xm(const float* __restrict__ X,
                                            float* __restrict__ Y) {
    const int b = blockIdx.z;
    const int bs = blockIdx.x * 128, bo = blockIdx.y * 128;
    const float* Xb = X + (size_t)b * NS * ND;
    const float* Mb = g_M + (size_t)b * ND * ND;
    float* Yb = Y + (size_t)b * NS * ND;

    __shared__ __nv_bfloat16 Ah[2][128][KLD], Al[2][128][KLD];
    __shared__ __nv_bfloat16 Bh[2][16][NLD], Bl[2][16][NLD];

    const int t = threadIdx.x;
    const int wid = t >> 5;
    const int m0 = (wid & 1) * 64, n0 = (wid >> 1) * 32;

    AccFrag acc[4][2];
#pragma unroll
    for (int i = 0; i < 4; i++)
#pragma unroll
        for (int j = 0; j < 2; j++) wmma::fill_fragment(acc[i][j], 0.0f);

#pragma unroll
    for (int l = 0; l < 2; l++) {
        int e = t + l * 256;
        int r = e >> 2, kg = (e & 3) << 2;
        uint2 h, lo;
        split4(*(const float4*)&Xb[(size_t)(bs + r) * ND + kg], h, lo);
        *(uint2*)&Ah[0][r][kg] = h; *(uint2*)&Al[0][r][kg] = lo;
        int row = e >> 5, col4 = e & 31;
        split4(*(const float4*)&Mb[(size_t)row * ND + bo + col4 * 4], h, lo);
        *(uint2*)&Bh[0][row][col4 * 4] = h; *(uint2*)&Bl[0][row][col4 * 4] = lo;
    }
    __syncthreads();

    const int T = ND / 16;
    for (int ti = 0; ti < T; ti++) {
        const int cur = ti & 1;
        float4 ra[2], rb[2];
        const bool more = (ti + 1 < T);
        if (more) {
            int d0 = (ti + 1) * 16;
#pragma unroll
            for (int l = 0; l < 2; l++) {
                int e = t + l * 256;
                int r = e >> 2, kg = (e & 3) << 2;
                ra[l] = *(const float4*)&Xb[(size_t)(bs + r) * ND + d0 + kg];
                int row = e >> 5, col4 = e & 31;
                rb[l] = *(const float4*)&Mb[(size_t)(d0 + row) * ND + bo + col4 * 4];
            }
        }
        {
            wmma::fragment<wmma::matrix_a, 16, 16, 16, __nv_bfloat16, wmma::row_major> ah[4], al[4];
            wmma::fragment<wmma::matrix_b, 16, 16, 16, __nv_bfloat16, wmma::row_major> bh[2], bl[2];
#pragma unroll
            for (int i = 0; i < 4; i++) {
                wmma::load_matrix_sync(ah[i], &Ah[cur][m0 + 16 * i][0], KLD);
                wmma::load_matrix_sync(al[i], &Al[cur][m0 + 16 * i][0], KLD);
            }
#pragma unroll
            for (int j = 0; j < 2; j++) {
                wmma::load_matrix_sync(bh[j], &Bh[cur][0][n0 + 16 * j], NLD);
                wmma::load_matrix_sync(bl[j], &Bl[cur][0][n0 + 16 * j], NLD);
            }
#pragma unroll
            for (int i = 0; i < 4; i++)
#pragma unroll
                for (int j = 0; j < 2; j++) {
                    wmma::mma_sync(acc[i][j], ah[i], bh[j], acc[i][j]);
                    wmma::mma_sync(acc[i][j], ah[i], bl[j], acc[i][j]);
                    wmma::mma_sync(acc[i][j], al[i], bh[j], acc[i][j]);
                }
        }
        if (more) {
            int nxt = cur ^ 1;
#pragma unroll
            for (int l = 0; l < 2; l++) {
                int e = t + l * 256;
                int r = e >> 2, kg = (e & 3) << 2;
                uint2 h, lo;
                split4(ra[l], h, lo);
                *(uint2*)&Ah[nxt][r][kg] = h; *(uint2*)&Al[nxt][r][kg] = lo;
                int row = e >> 5, col4 = e & 31;
                split4(rb[l], h, lo);
                *(uint2*)&Bh[nxt][row][col4 * 4] = h; *(uint2*)&Bl[nxt][row][col4 * 4] = lo;
            }
        }
        __syncthreads();
    }

#pragma unroll
    for (int i = 0; i < 4; i++)
#pragma unroll
        for (int j = 0; j < 2; j++)
            wmma::store_matrix_sync(&Yb[(size_t)(bs + m0 + 16 * i) * ND + bo + n0 + 16 * j],
                                    acc[i][j], ND, wmma::mem_row_major);
}

// ---------------------------------------------------------------------------
extern "C" void kernel_launch(void* const* d_in, const int* in_sizes, int n_in,
                              void* d_out, int out_size) {
    const float* x  = (const float*)d_in[0];
    const float* Wq = (const float*)d_in[1];
    const float* Wk = (const float*)d_in[2];
    const float* Wv = (const float*)d_in[3];
    const float* Wo = (const float*)d_in[4];
    float* y = (float*)d_out;

    // 1) Gram matrices: G_b = X_b^T X_b (symmetric, 36 block pairs)
    k_xtx<<<dim3(36, 1, NB), 256>>>(x);
    // 2) U_b = G_b Wq^T
    k_abt<<<dim3(8, 8, NB), 256>>>(Wq, 0);
    // 3) per-head scores + softmax + P_h = Wv_h^T A_h
    k_head<<<dim3(NH, NB), 256>>>(Wk, Wv);
    // 4) M_b = P_b Wo^T
    k_abt<<<dim3(8, 8, NB), 256>>>(Wo, 1);
    // 5) Y_b = X_b M_b
    k_xm<<<dim3(32, 8, NB), 256>>>(x, y);
}